// round 10
// baseline (speedup 1.0000x reference)
#include <cuda_runtime.h>
#include <math.h>

#define Tt   512
#define Bb   64
#define INN  128
#define Hh   512
#define Ll   3
#define OUTN 128

// ---------------- scratch (device globals: no runtime allocation) ----------
__device__ float g_bufA[Tt * Bb * Hh];   // 64 MB activation ping
__device__ float g_bufB[Tt * Bb * Hh];   // 64 MB activation pong
__device__ unsigned g_prog[3][128];      // per-layer scan progress flags

// ---------------- packed fp32x2 helpers (B300 FFMA2 path) ------------------
typedef unsigned long long ull;
#define FMA2(d, a, b) asm("fma.rn.f32x2 %0, %1, %2, %0;" : "+l"(d) : "l"(a), "l"(b))
#define UNPK(lo, hi, p) asm("mov.b64 {%0, %1}, %2;" : "=f"(lo), "=f"(hi) : "l"(p))

__device__ __forceinline__ unsigned cvta_smem(const void* p) {
    unsigned a;
    asm("{ .reg .u64 t; cvta.to.shared.u64 t, %1; cvt.u32.u64 %0, t; }"
        : "=r"(a) : "l"(p));
    return a;
}
__device__ __forceinline__ unsigned mapa_u32(unsigned addr, unsigned rank) {
    unsigned r;
    asm("mapa.shared::cluster.u32 %0, %1, %2;" : "=r"(r) : "r"(addr), "r"(rank));
    return r;
}
// bulk smem -> peer smem copy, tx-accounted on the PEER's mbarrier
__device__ __forceinline__ void bulk_s2c(unsigned dst, unsigned src,
                                         unsigned bytes, unsigned rbar) {
    asm volatile(
        "cp.async.bulk.shared::cluster.shared::cta.mbarrier::complete_tx::bytes "
        "[%0], [%1], %2, [%3];"
        :: "r"(dst), "r"(src), "r"(bytes), "r"(rbar) : "memory");
}
#define MBAR_INIT(a, n) \
    asm volatile("mbarrier.init.shared.b64 [%0], %1;" :: "r"(a), "r"(n) : "memory")
#define MBAR_EXPECT_TX(a, tx) \
    asm volatile("mbarrier.arrive.expect_tx.shared.b64 _, [%0], %1;" \
                 :: "r"(a), "r"(tx) : "memory")
// cta-scope acquire wait: data is delivered into LOCAL smem by the async
// engine (TMA-like), so cta scope suffices (vs ~490-cyc cluster-scope wait).
#define MBAR_WAIT_CTA(a, ph) do {                                              \
    unsigned _dn;                                                              \
    asm volatile("{\n\t.reg .pred p;\n\t"                                      \
        "mbarrier.try_wait.parity.acquire.cta.shared::cta.b64 p, [%1], %2;\n\t" \
        "selp.b32 %0, 1, 0, p;\n\t}"                                           \
        : "=r"(_dn) : "r"(a), "r"(ph) : "memory");                             \
    while (!_dn) {                                                             \
        asm volatile("{\n\t.reg .pred p;\n\t"                                  \
            "mbarrier.try_wait.parity.acquire.cta.shared::cta.b64 p, [%1], %2, 0x989680;\n\t" \
            "selp.b32 %0, 1, 0, p;\n\t}"                                       \
            : "=r"(_dn) : "r"(a), "r"(ph) : "memory");                         \
    }                                                                          \
} while (0)

// ---------------- SGEMM (layer-0 input proj): Y = X @ W^T + b1 + b2 --------
template <int K>
__global__ __launch_bounds__(256, 2) void sgemm_bias(
    const float* __restrict__ X, const float* __restrict__ W,
    const float* __restrict__ b1, const float* __restrict__ b2,
    float* __restrict__ Y, int N, unsigned* reset128)
{
    constexpr int BM = 128, BN = 64, BK = 32, SA = BK + 2;
    __shared__ float Asm[BM * SA];
    __shared__ float Wsm[BN * SA];

    const int tid = threadIdx.x;
    if (reset128 && blockIdx.x == 0 && blockIdx.y == 0 && tid < 128)
        reset128[tid] = 0;                      // replay-safe flag reset
    const int r = tid >> 4;
    const int c = tid & 15;
    const int m0 = blockIdx.y * BM;
    const int n0 = blockIdx.x * BN;

    ull acc[8][4];
#pragma unroll
    for (int i = 0; i < 8; i++)
#pragma unroll
        for (int j = 0; j < 4; j++) acc[i][j] = 0ull;

    for (int k0 = 0; k0 < K; k0 += BK) {
#pragma unroll
        for (int i = 0; i < 4; i++) {
            int f = tid + i * 256;
            int m = f >> 3, kq = f & 7;
            float4 v = *(const float4*)&X[(size_t)(m0 + m) * K + k0 + kq * 4];
            float* d = &Asm[m * SA + kq * 4];
            *(float2*)&d[0] = make_float2(v.x, v.y);
            *(float2*)&d[2] = make_float2(v.z, v.w);
        }
#pragma unroll
        for (int i = 0; i < 2; i++) {
            int f = tid + i * 256;
            int n = f >> 3, kq = f & 7;
            float4 v = *(const float4*)&W[(size_t)(n0 + n) * K + k0 + kq * 4];
            float* d = &Wsm[n * SA + kq * 4];
            *(float2*)&d[0] = make_float2(v.x, v.y);
            *(float2*)&d[2] = make_float2(v.z, v.w);
        }
        __syncthreads();

#pragma unroll
        for (int kp = 0; kp < BK / 2; kp++) {
            ull a[8], b[4];
#pragma unroll
            for (int i = 0; i < 8; i++)
                a[i] = *(const ull*)&Asm[(r * 8 + i) * SA + 2 * kp];
#pragma unroll
            for (int j = 0; j < 4; j++)
                b[j] = *(const ull*)&Wsm[(j * 16 + c) * SA + 2 * kp];
#pragma unroll
            for (int i = 0; i < 8; i++)
#pragma unroll
                for (int j = 0; j < 4; j++) FMA2(acc[i][j], a[i], b[j]);
        }
        __syncthreads();
    }

#pragma unroll
    for (int i = 0; i < 8; i++) {
        int m = m0 + r * 8 + i;
#pragma unroll
        for (int j = 0; j < 4; j++) {
            int n = n0 + j * 16 + c;
            float lo, hi;
            UNPK(lo, hi, acc[i][j]);
            float bias = b1[n];
            if (b2) bias += b2[n];
            Y[(size_t)m * N + n] = lo + hi + bias;
        }
    }
}

// ---------------- overlapped GEMM (runs concurrently with a scan) ----------
// Y[32768,N] = X[32768,512] @ W[N,512]^T + b1(+b2). BM=64 (=1 timestep),
// BN=64, tiles gated on the producing scan's progress flags (128 entries,
// each advances by 8 timesteps). <=85 regs (launch_bounds 256,3) so a CTA
// co-resides with a 166-reg scan CTA on the same SM.
__global__ __launch_bounds__(256, 3) void gemmB(
    const float* __restrict__ X, const float* __restrict__ W,
    const float* __restrict__ b1, const float* __restrict__ b2,
    float* __restrict__ Y, int N,
    const unsigned* __restrict__ prog, unsigned* resetNext)
{
    constexpr int K = 512, SA = 34;
    __shared__ float Xs[64 * SA];
    __shared__ float Ws[64 * SA];
    __shared__ unsigned s_ready;

    const int tid = threadIdx.x;
    if (resetNext && blockIdx.x == 0 && tid < 128) resetNext[tid] = 0;
    if (tid == 0) s_ready = 0;
    __syncthreads();

    const int r = tid >> 4, c = tid & 15;
    const int NTN = N >> 6;
    const int ntiles = 512 * NTN;
    unsigned ready = 0;

    for (int tile = blockIdx.x; tile < ntiles; tile += gridDim.x) {
        const int mt = tile / NTN, nt = tile - mt * NTN;
        const int m0 = mt * 64, n0 = nt * 64;

        // ---- gate: all 128 scan CTAs must have published timestep mt ----
        if (ready < (unsigned)(mt + 1)) {
            if (tid == 0) {
                unsigned need = (unsigned)(mt + 1);
                unsigned mn = s_ready;
                while (mn < need) {
                    mn = 0xffffffffu;
#pragma unroll
                    for (int i = 0; i < 32; i++) {
                        uint4 f = __ldcg((const uint4*)(prog + i * 4));
                        mn = min(mn, min(min(f.x, f.y), min(f.z, f.w)));
                    }
                    if (mn < need) __nanosleep(512);
                }
                s_ready = mn;
            }
            __syncthreads();
            ready = s_ready;
        }

        ull acc[4][4];
#pragma unroll
        for (int i = 0; i < 4; i++)
#pragma unroll
            for (int j = 0; j < 4; j++) acc[i][j] = 0ull;

        for (int k0 = 0; k0 < K; k0 += 32) {
#pragma unroll
            for (int i = 0; i < 2; i++) {
                int f = tid + i * 256;
                int m = f >> 3, kq = f & 7;
                float4 v = __ldcg((const float4*)&X[(size_t)(m0 + m) * K + k0 + kq * 4]);
                float* d = &Xs[m * SA + kq * 4];
                *(float2*)&d[0] = make_float2(v.x, v.y);
                *(float2*)&d[2] = make_float2(v.z, v.w);
                float4 wv = *(const float4*)&W[(size_t)(n0 + m) * K + k0 + kq * 4];
                d = &Ws[m * SA + kq * 4];
                *(float2*)&d[0] = make_float2(wv.x, wv.y);
                *(float2*)&d[2] = make_float2(wv.z, wv.w);
            }
            __syncthreads();
#pragma unroll
            for (int kp = 0; kp < 16; kp++) {
                ull a[4], b[4];
#pragma unroll
                for (int i = 0; i < 4; i++)
                    a[i] = *(const ull*)&Xs[(r * 4 + i) * SA + 2 * kp];
#pragma unroll
                for (int j = 0; j < 4; j++)
                    b[j] = *(const ull*)&Ws[(j * 16 + c) * SA + 2 * kp];
#pragma unroll
                for (int i = 0; i < 4; i++)
#pragma unroll
                    for (int j = 0; j < 4; j++) FMA2(acc[i][j], a[i], b[j]);
            }
            __syncthreads();
        }

#pragma unroll
        for (int i = 0; i < 4; i++) {
            int m = m0 + r * 4 + i;
#pragma unroll
            for (int j = 0; j < 4; j++) {
                int n = n0 + j * 16 + c;
                float lo, hi;
                UNPK(lo, hi, acc[i][j]);
                float bias = b1[n];
                if (b2) bias += b2[n];
                Y[(size_t)m * N + n] = lo + hi + bias;
            }
        }
    }
}

// ---------------- recurrent scan: partial-exchange dataflow (R8 base) ------
// 128 CTAs = 16 clusters (4 batches) x 8 ranks. Rank r owns j-slice r AND
// k-slice r. Warp w sends ONE 1KB partial block to peer w per step. Changes
// vs R8: cta-scope waits, progress flags every 8 steps for overlapped GEMMs.
__global__ __launch_bounds__(256) __cluster_dims__(8, 1, 1)
void rnn_scan(
    float* __restrict__ act,         // [T,B,H] pre -> overwritten with ys
    const float* __restrict__ Whh,   // [H,H] row-major (j,k)
    const float* __restrict__ h0l,   // [B,H]
    float* __restrict__ hout,        // [B,H] final hidden
    unsigned* __restrict__ prog)     // [128] progress flags
{
    __shared__ __align__(16) float hprt[2][8][256];  // recv partials
    __shared__ __align__(16) float sout[2][8][256];  // outgoing partials
    __shared__ __align__(16) float hstage[2][256];   // own h chunk
    __shared__ __align__(8)  ull  mbarr[2];

    const int tid  = threadIdx.x;
    const int lane = tid & 31;
    const int w    = tid >> 5;       // warp = destination rank
    const int jg   = blockIdx.x & 7; // cluster rank: owns j & k slice jg
    const int bg   = blockIdx.x >> 3;
    const int b0   = bg * 4;

    // persistent W slice in registers: rows j = 64w+2l(+1), cols k-slice jg
    ull w0[32], w1[32];
    {
        const float* r0 = &Whh[(size_t)(64 * w + 2 * lane + 0) * Hh + 64 * jg];
        const float* r1 = &Whh[(size_t)(64 * w + 2 * lane + 1) * Hh + 64 * jg];
#pragma unroll
        for (int kp = 0; kp < 32; kp++) {
            w0[kp] = *(const ull*)&r0[2 * kp];
            w1[kp] = *(const ull*)&r1[2 * kp];
        }
    }

    const unsigned hprt_a = cvta_smem(&hprt[0][0][0]);
    const unsigned sout_a = cvta_smem(&sout[0][0][0]);
    const unsigned bar_a  = cvta_smem(&mbarr[0]);

    const unsigned peer_hprt = mapa_u32(hprt_a, w) + (unsigned)jg * 1024u;
    const unsigned peer_bar  = mapa_u32(bar_a, w);

    if (tid < 2) MBAR_INIT(bar_a + tid * 8, 1);
    if (tid == 0) {
        asm volatile("fence.mbarrier_init.release.cluster;" ::: "memory");
        MBAR_EXPECT_TX(bar_a, 8192);           // arm barrier for step 0
    }

    const int ob = tid >> 6;
    const int oj = tid & 63;
    const int gb = b0 + ob;
    const int gj = 64 * jg + oj;

    hstage[0][tid] = h0l[(size_t)gb * Hh + gj];
    __syncthreads();
    asm volatile("barrier.cluster.arrive.aligned;" ::: "memory");
    asm volatile("barrier.cluster.wait.aligned;" ::: "memory");

    unsigned par0 = 0, par1 = 0;

    for (int t = 0; t < Tt; t++) {
        const int buf = t & 1, nb = buf ^ 1;
        size_t gidx = (size_t)t * Bb * Hh + (size_t)gb * Hh + gj;
        float pre = act[gidx];                         // overlaps FFMA

        if (tid == 0 && t < Tt - 1)
            MBAR_EXPECT_TX(bar_a + nb * 8, 8192);

        // ---- FFMA: partial for rank w's 64 outputs over our 64-k slice ----
        const float* hb = &hstage[buf][0];
        ull a00 = 0, a01 = 0, a10 = 0, a11 = 0;
        ull a20 = 0, a21 = 0, a30 = 0, a31 = 0;
#pragma unroll
        for (int kp = 0; kp < 32; kp++) {
            ull wa = w0[kp], wb = w1[kp];
            ull hb0 = *(const ull*)&hb[0 * 64 + 2 * kp];
            ull hb1 = *(const ull*)&hb[1 * 64 + 2 * kp];
            ull hb2 = *(const ull*)&hb[2 * 64 + 2 * kp];
            ull hb3 = *(const ull*)&hb[3 * 64 + 2 * kp];
            FMA2(a00, wa, hb0); FMA2(a01, wb, hb0);
            FMA2(a10, wa, hb1); FMA2(a11, wb, hb1);
            FMA2(a20, wa, hb2); FMA2(a21, wb, hb2);
            FMA2(a30, wa, hb3); FMA2(a31, wb, hb3);
        }

        // ---- stage + send this warp's 1KB partial block to peer w ----
        {
            float lo, hi, s0, s1;
            float* sp = &sout[buf][w][2 * lane];
            UNPK(lo, hi, a00); s0 = lo + hi; UNPK(lo, hi, a01); s1 = lo + hi;
            *(float2*)&sp[0 * 64] = make_float2(s0, s1);
            UNPK(lo, hi, a10); s0 = lo + hi; UNPK(lo, hi, a11); s1 = lo + hi;
            *(float2*)&sp[1 * 64] = make_float2(s0, s1);
            UNPK(lo, hi, a20); s0 = lo + hi; UNPK(lo, hi, a21); s1 = lo + hi;
            *(float2*)&sp[2 * 64] = make_float2(s0, s1);
            UNPK(lo, hi, a30); s0 = lo + hi; UNPK(lo, hi, a31); s1 = lo + hi;
            *(float2*)&sp[3 * 64] = make_float2(s0, s1);
        }
        __syncwarp();
        if (lane == 0) {
            asm volatile("fence.proxy.async.shared::cta;" ::: "memory");
            bulk_s2c(peer_hprt + (unsigned)buf * 8192u,
                     sout_a + (unsigned)(buf * 8192 + w * 1024),
                     1024u, peer_bar + (unsigned)buf * 8u);
        }

        // ---- wait all 8 partial blocks (cta-scope acquire) ----
        if (buf == 0) { MBAR_WAIT_CTA(bar_a, par0); par0 ^= 1; }
        else          { MBAR_WAIT_CTA(bar_a + 8, par1); par1 ^= 1; }

        float s = 0.f;
#pragma unroll
        for (int q = 0; q < 8; q++) s += hprt[buf][q][tid];

        float v = tanhf(s + pre);
        act[gidx] = v;                                  // ys in place

        if (t < Tt - 1) hstage[nb][tid] = v;            // next step's k-input
        else            hout[(size_t)gb * Hh + gj] = v; // final hidden
        __syncthreads();

        // publish progress for the overlapped consumer GEMM (every 8 steps)
        if (((t & 7) == 7) && tid == 0) {
            __threadfence();
            *(volatile unsigned*)&prog[blockIdx.x] = (unsigned)(t + 1);
        }
    }

    asm volatile("barrier.cluster.arrive.aligned;" ::: "memory");
    asm volatile("barrier.cluster.wait.aligned;" ::: "memory");
}

// ---------------- launch ----------------------------------------------------
extern "C" void kernel_launch(void* const* d_in, const int* in_sizes, int n_in,
                              void* d_out, int out_size)
{
    (void)in_sizes; (void)n_in; (void)out_size;
    const float* x     = (const float*)d_in[0];   // [T,B,IN]
    const float* h0    = (const float*)d_in[1];   // [L,B,H]
    const float* W_ih0 = (const float*)d_in[2];   // [H,IN]
    const float* W_ihr = (const float*)d_in[3];   // [L-1,H,H]
    const float* W_hh  = (const float*)d_in[4];   // [L,H,H]
    const float* b_ih  = (const float*)d_in[5];   // [L,H]
    const float* b_hh  = (const float*)d_in[6];   // [L,H]
    const float* lin_W = (const float*)d_in[7];   // [OUT,H]
    const float* lin_b = (const float*)d_in[8];   // [OUT]

    float* out   = (float*)d_out;                       // [T,B,OUT]
    float* h_out = out + (size_t)Tt * Bb * OUTN;        // [L,B,H]

    float *bufA, *bufB;
    unsigned* prog;
    cudaGetSymbolAddress((void**)&bufA, g_bufA);
    cudaGetSymbolAddress((void**)&bufB, g_bufB);
    cudaGetSymbolAddress((void**)&prog, g_prog);
    unsigned* p0 = prog;
    unsigned* p1 = prog + 128;
    unsigned* p2 = prog + 256;

    // one-time handles (created on the eager correctness call, before capture;
    // identical device work on every call)
    static cudaStream_t s2 = nullptr;
    static cudaEvent_t ev0, ev1, ev2, ev3;
    if (!s2) {
        cudaStreamCreateWithFlags(&s2, cudaStreamNonBlocking);
        cudaEventCreateWithFlags(&ev0, cudaEventDisableTiming);
        cudaEventCreateWithFlags(&ev1, cudaEventDisableTiming);
        cudaEventCreateWithFlags(&ev2, cudaEventDisableTiming);
        cudaEventCreateWithFlags(&ev3, cudaEventDisableTiming);
    }

    dim3 blk(256);
    const int MB = (Tt * Bb) / 128;     // 256 M-blocks
    const int NG = 160;                 // overlapped-GEMM CTAs

    // G0: layer-0 input projection (also resets layer-0 progress flags)
    sgemm_bias<INN><<<dim3(Hh / 64, MB), blk>>>(x, W_ih0, b_ih, b_hh, bufA, Hh, p0);

    // fork: s2 runs gemm(l+1) concurrently with scan(l)
    cudaEventRecord(ev0, 0);
    cudaStreamWaitEvent(s2, ev0, 0);

    // layer 0 scan  ||  layer-1 input projection (gated on p0, resets p1)
    rnn_scan<<<128, blk>>>(bufA, W_hh, h0, h_out, p0);
    gemmB<<<NG, blk, 0, s2>>>(bufA, W_ihr, b_ih + Hh, b_hh + Hh, bufB, Hh, p0, p1);
    cudaEventRecord(ev1, s2);
    cudaStreamWaitEvent(0, ev1, 0);

    // layer 1 scan  ||  layer-2 input projection (gated on p1, resets p2)
    rnn_scan<<<128, blk>>>(bufB, W_hh + Hh * Hh, h0 + Bb * Hh,
                           h_out + Bb * Hh, p1);
    gemmB<<<NG, blk, 0, s2>>>(bufB, W_ihr + Hh * Hh, b_ih + 2 * Hh,
                              b_hh + 2 * Hh, bufA, Hh, p1, p2);
    cudaEventRecord(ev2, s2);
    cudaStreamWaitEvent(0, ev2, 0);

    // layer 2 scan  ||  final linear (gated on p2)
    rnn_scan<<<128, blk>>>(bufA, W_hh + 2 * Hh * Hh, h0 + 2 * Bb * Hh,
                           h_out + 2 * Bb * Hh, p2);
    gemmB<<<NG, blk, 0, s2>>>(bufA, lin_W, lin_b, nullptr, out, OUTN, p2, nullptr);
    cudaEventRecord(ev3, s2);
    cudaStreamWaitEvent(0, ev3, 0);
}

// round 11
// speedup vs baseline: 1.2494x; 1.2494x over previous
#include <cuda_runtime.h>
#include <math.h>

#define Tt   512
#define Bb   64
#define INN  128
#define Hh   512
#define Ll   3
#define OUTN 128

// ---------------- scratch (device globals: no runtime allocation) ----------
__device__ float g_bufA[Tt * Bb * Hh];   // 64 MB activation ping
__device__ float g_bufB[Tt * Bb * Hh];   // 64 MB activation pong

// ---------------- packed fp32x2 helpers (B300 FFMA2 path) ------------------
typedef unsigned long long ull;
#define FMA2(d, a, b) asm("fma.rn.f32x2 %0, %1, %2, %0;" : "+l"(d) : "l"(a), "l"(b))
#define UNPK(lo, hi, p) asm("mov.b64 {%0, %1}, %2;" : "=f"(lo), "=f"(hi) : "l"(p))

__device__ __forceinline__ unsigned cvta_smem(const void* p) {
    unsigned a;
    asm("{ .reg .u64 t; cvta.to.shared.u64 t, %1; cvt.u32.u64 %0, t; }"
        : "=r"(a) : "l"(p));
    return a;
}
__device__ __forceinline__ unsigned mapa_u32(unsigned addr, unsigned rank) {
    unsigned r;
    asm("mapa.shared::cluster.u32 %0, %1, %2;" : "=r"(r) : "r"(addr), "r"(rank));
    return r;
}
// bulk smem -> peer smem copy, tx-accounted on the PEER's mbarrier
__device__ __forceinline__ void bulk_s2c(unsigned dst, unsigned src,
                                         unsigned bytes, unsigned rbar) {
    asm volatile(
        "cp.async.bulk.shared::cluster.shared::cta.mbarrier::complete_tx::bytes "
        "[%0], [%1], %2, [%3];"
        :: "r"(dst), "r"(src), "r"(bytes), "r"(rbar) : "memory");
}
#define MBAR_INIT(a, n) \
    asm volatile("mbarrier.init.shared.b64 [%0], %1;" :: "r"(a), "r"(n) : "memory")
#define MBAR_EXPECT_TX(a, tx) \
    asm volatile("mbarrier.arrive.expect_tx.shared.b64 _, [%0], %1;" \
                 :: "r"(a), "r"(tx) : "memory")
// cta-scope acquire wait (standard TMA-consumer pattern): the async engine
// delivered the data into LOCAL smem and tx-updated the LOCAL barrier, so
// cta-scope acquire suffices. Cluster-scope waits cost ~490 cyc (UCGABAR).
#define MBAR_WAIT_CTA(a, ph) do {                                              \
    unsigned _dn;                                                              \
    asm volatile("{\n\t.reg .pred p;\n\t"                                      \
        "mbarrier.try_wait.parity.acquire.cta.shared::cta.b64 p, [%1], %2;\n\t" \
        "selp.b32 %0, 1, 0, p;\n\t}"                                           \
        : "=r"(_dn) : "r"(a), "r"(ph) : "memory");                             \
    while (!_dn) {                                                             \
        asm volatile("{\n\t.reg .pred p;\n\t"                                  \
            "mbarrier.try_wait.parity.acquire.cta.shared::cta.b64 p, [%1], %2, 0x989680;\n\t" \
            "selp.b32 %0, 1, 0, p;\n\t}"                                       \
            : "=r"(_dn) : "r"(a), "r"(ph) : "memory");                         \
    }                                                                          \
} while (0)

// ---------------- SGEMM: Y[M,N] = X[M,K] @ W[N,K]^T + b1(+b2) --------------
// (unchanged from R8: measured ~61% of the fp32 FFMA2 roofline)
template <int K>
__global__ __launch_bounds__(256, 2) void sgemm_bias(
    const float* __restrict__ X, const float* __restrict__ W,
    const float* __restrict__ b1, const float* __restrict__ b2,
    float* __restrict__ Y, int N)
{
    constexpr int BM = 128, BN = 64, BK = 32, SA = BK + 2;
    __shared__ float Asm[BM * SA];
    __shared__ float Wsm[BN * SA];

    const int tid = threadIdx.x;
    const int r = tid >> 4;
    const int c = tid & 15;
    const int m0 = blockIdx.y * BM;
    const int n0 = blockIdx.x * BN;

    ull acc[8][4];
#pragma unroll
    for (int i = 0; i < 8; i++)
#pragma unroll
        for (int j = 0; j < 4; j++) acc[i][j] = 0ull;

    for (int k0 = 0; k0 < K; k0 += BK) {
#pragma unroll
        for (int i = 0; i < 4; i++) {
            int f = tid + i * 256;
            int m = f >> 3, kq = f & 7;
            float4 v = *(const float4*)&X[(size_t)(m0 + m) * K + k0 + kq * 4];
            float* d = &Asm[m * SA + kq * 4];
            *(float2*)&d[0] = make_float2(v.x, v.y);
            *(float2*)&d[2] = make_float2(v.z, v.w);
        }
#pragma unroll
        for (int i = 0; i < 2; i++) {
            int f = tid + i * 256;
            int n = f >> 3, kq = f & 7;
            float4 v = *(const float4*)&W[(size_t)(n0 + n) * K + k0 + kq * 4];
            float* d = &Wsm[n * SA + kq * 4];
            *(float2*)&d[0] = make_float2(v.x, v.y);
            *(float2*)&d[2] = make_float2(v.z, v.w);
        }
        __syncthreads();

#pragma unroll
        for (int kp = 0; kp < BK / 2; kp++) {
            ull a[8], b[4];
#pragma unroll
            for (int i = 0; i < 8; i++)
                a[i] = *(const ull*)&Asm[(r * 8 + i) * SA + 2 * kp];
#pragma unroll
            for (int j = 0; j < 4; j++)
                b[j] = *(const ull*)&Wsm[(j * 16 + c) * SA + 2 * kp];
#pragma unroll
            for (int i = 0; i < 8; i++)
#pragma unroll
                for (int j = 0; j < 4; j++) FMA2(acc[i][j], a[i], b[j]);
        }
        __syncthreads();
    }

#pragma unroll
    for (int i = 0; i < 8; i++) {
        int m = m0 + r * 8 + i;
#pragma unroll
        for (int j = 0; j < 4; j++) {
            int n = n0 + j * 16 + c;
            float lo, hi;
            UNPK(lo, hi, acc[i][j]);
            float bias = b1[n];
            if (b2) bias += b2[n];
            Y[(size_t)m * N + n] = lo + hi + bias;
        }
    }
}

// ---------------- recurrent scan: partial-exchange, split early sends ------
// 128 CTAs = 16 clusters (4 batches) x 8 ranks. Rank r owns j-slice r AND
// k-slice r (diagonal ownership -> h never broadcast). Per step, warp w:
//   pass 1: partial for rank w's outputs, batches {0,1} -> send 512B
//   pass 2: batches {2,3}                               -> send 512B
// so half the DSMEM drain overlaps pass-2 FFMA. Consumer does ONE cta-scope
// acquire wait (16 x 512B tx = 8192), sums 8 partials, tanh. One
// __syncthreads per step.
__global__ __launch_bounds__(256) __cluster_dims__(8, 1, 1)
void rnn_scan(
    float* __restrict__ act,         // [T,B,H] pre -> overwritten with ys
    const float* __restrict__ Whh,   // [H,H] row-major (j,k)
    const float* __restrict__ h0l,   // [B,H]
    float* __restrict__ hout)        // [B,H] final hidden
{
    __shared__ __align__(16) float hprt[2][8][256];  // recv partials [buf][src][b*64+j']
    __shared__ __align__(16) float sout[2][8][256];  // outgoing [buf][dest=w][b*64+j']
    __shared__ __align__(16) float hstage[2][256];   // own h chunk [buf][b*64+k']
    __shared__ __align__(8)  ull  mbarr[2];

    const int tid  = threadIdx.x;
    const int lane = tid & 31;
    const int w    = tid >> 5;       // warp = destination rank (j-block 64w..)
    const int jg   = blockIdx.x & 7; // cluster rank: owns j & k slice jg
    const int bg   = blockIdx.x >> 3;
    const int b0   = bg * 4;

    // ---- persistent W slice in registers ----
    // warp w, lane l: rows j = 64w + 2l (+1), cols k = [64*jg, 64*jg+64)
    ull w0[32], w1[32];
    {
        const float* r0 = &Whh[(size_t)(64 * w + 2 * lane + 0) * Hh + 64 * jg];
        const float* r1 = &Whh[(size_t)(64 * w + 2 * lane + 1) * Hh + 64 * jg];
#pragma unroll
        for (int kp = 0; kp < 32; kp++) {
            w0[kp] = *(const ull*)&r0[2 * kp];
            w1[kp] = *(const ull*)&r1[2 * kp];
        }
    }

    const unsigned hprt_a = cvta_smem(&hprt[0][0][0]);
    const unsigned sout_a = cvta_smem(&sout[0][0][0]);
    const unsigned bar_a  = cvta_smem(&mbarr[0]);

    // warp w sends to peer rank w; our source-block index in peer's hprt is jg
    const unsigned peer_hprt = mapa_u32(hprt_a, w) + (unsigned)jg * 1024u;
    const unsigned peer_bar  = mapa_u32(bar_a, w);

    if (tid < 2) MBAR_INIT(bar_a + tid * 8, 1);
    if (tid == 0) {
        asm volatile("fence.mbarrier_init.release.cluster;" ::: "memory");
        MBAR_EXPECT_TX(bar_a, 8192);           // arm barrier for step 0
    }

    // output/ownership mapping: thread tid <-> (b = tid>>6, j' = tid&63)
    const int ob = tid >> 6;
    const int oj = tid & 63;
    const int gb = b0 + ob;
    const int gj = 64 * jg + oj;

    // bootstrap: own h_{-1} chunk (k-input chunk) into hstage[0]
    hstage[0][tid] = h0l[(size_t)gb * Hh + gj];
    __syncthreads();
    asm volatile("barrier.cluster.arrive.aligned;" ::: "memory");
    asm volatile("barrier.cluster.wait.aligned;" ::: "memory");

    unsigned par0 = 0, par1 = 0;

    for (int t = 0; t < Tt; t++) {
        const int buf = t & 1, nb = buf ^ 1;
        size_t gidx = (size_t)t * Bb * Hh + (size_t)gb * Hh + gj;
        float pre = act[gidx];                         // overlaps FFMA

        // arm next step's barrier
        if (tid == 0 && t < Tt - 1)
            MBAR_EXPECT_TX(bar_a + nb * 8, 8192);

        const float* hb = &hstage[buf][0];
        const unsigned dst_base = peer_hprt + (unsigned)buf * 8192u;
        const unsigned src_base = sout_a + (unsigned)(buf * 8192 + w * 1024);
        const unsigned bar_dst  = peer_bar + (unsigned)buf * 8u;

        // ======== pass 1: batches 0,1 -> early 512B send ========
        {
            ull a00 = 0, a01 = 0, a10 = 0, a11 = 0;
#pragma unroll
            for (int kp = 0; kp < 32; kp++) {
                ull wa = w0[kp], wb = w1[kp];
                ull hb0 = *(const ull*)&hb[0 * 64 + 2 * kp];   // lane-broadcast
                ull hb1 = *(const ull*)&hb[1 * 64 + 2 * kp];
                FMA2(a00, wa, hb0); FMA2(a01, wb, hb0);
                FMA2(a10, wa, hb1); FMA2(a11, wb, hb1);
            }
            float lo, hi, s0, s1;
            float* sp = &sout[buf][w][2 * lane];
            UNPK(lo, hi, a00); s0 = lo + hi; UNPK(lo, hi, a01); s1 = lo + hi;
            *(float2*)&sp[0 * 64] = make_float2(s0, s1);
            UNPK(lo, hi, a10); s0 = lo + hi; UNPK(lo, hi, a11); s1 = lo + hi;
            *(float2*)&sp[1 * 64] = make_float2(s0, s1);
            __syncwarp();
            if (lane == 0) {
                asm volatile("fence.proxy.async.shared::cta;" ::: "memory");
                bulk_s2c(dst_base, src_base, 512u, bar_dst);
            }
        }
        // ======== pass 2: batches 2,3 -> second 512B send ========
        {
            ull a20 = 0, a21 = 0, a30 = 0, a31 = 0;
#pragma unroll
            for (int kp = 0; kp < 32; kp++) {
                ull wa = w0[kp], wb = w1[kp];
                ull hb2 = *(const ull*)&hb[2 * 64 + 2 * kp];
                ull hb3 = *(const ull*)&hb[3 * 64 + 2 * kp];
                FMA2(a20, wa, hb2); FMA2(a21, wb, hb2);
                FMA2(a30, wa, hb3); FMA2(a31, wb, hb3);
            }
            float lo, hi, s0, s1;
            float* sp = &sout[buf][w][2 * lane];
            UNPK(lo, hi, a20); s0 = lo + hi; UNPK(lo, hi, a21); s1 = lo + hi;
            *(float2*)&sp[2 * 64] = make_float2(s0, s1);
            UNPK(lo, hi, a30); s0 = lo + hi; UNPK(lo, hi, a31); s1 = lo + hi;
            *(float2*)&sp[3 * 64] = make_float2(s0, s1);
            __syncwarp();
            if (lane == 0) {
                asm volatile("fence.proxy.async.shared::cta;" ::: "memory");
                bulk_s2c(dst_base + 512u, src_base + 512u, 512u, bar_dst);
            }
        }

        // ---- ONE cta-scope acquire wait for all 16 x 512B deliveries ----
        if (buf == 0) { MBAR_WAIT_CTA(bar_a, par0); par0 ^= 1; }
        else          { MBAR_WAIT_CTA(bar_a + 8, par1); par1 ^= 1; }

        float s = 0.f;
#pragma unroll
        for (int q = 0; q < 8; q++) s += hprt[buf][q][tid];

        float v = tanhf(s + pre);
        act[gidx] = v;                                  // ys in place

        if (t < Tt - 1) hstage[nb][tid] = v;            // next step's k-input
        else            hout[(size_t)gb * Hh + gj] = v; // final hidden
        __syncthreads();                                // publish hstage
    }

    // no peer may exit while another could still address its smem
    asm volatile("barrier.cluster.arrive.aligned;" ::: "memory");
    asm volatile("barrier.cluster.wait.aligned;" ::: "memory");
}

// ---------------- launch (serial, R8 style — overlap reverted) --------------
extern "C" void kernel_launch(void* const* d_in, const int* in_sizes, int n_in,
                              void* d_out, int out_size)
{
    (void)in_sizes; (void)n_in; (void)out_size;
    const float* x     = (const float*)d_in[0];   // [T,B,IN]
    const float* h0    = (const float*)d_in[1];   // [L,B,H]
    const float* W_ih0 = (const float*)d_in[2];   // [H,IN]
    const float* W_ihr = (const float*)d_in[3];   // [L-1,H,H]
    const float* W_hh  = (const float*)d_in[4];   // [L,H,H]
    const float* b_ih  = (const float*)d_in[5];   // [L,H]
    const float* b_hh  = (const float*)d_in[6];   // [L,H]
    const float* lin_W = (const float*)d_in[7];   // [OUT,H]
    const float* lin_b = (const float*)d_in[8];   // [OUT]

    float* out   = (float*)d_out;                       // [T,B,OUT]
    float* h_out = out + (size_t)Tt * Bb * OUTN;        // [L,B,H]

    float *bufA, *bufB;
    cudaGetSymbolAddress((void**)&bufA, g_bufA);
    cudaGetSymbolAddress((void**)&bufB, g_bufB);

    dim3 blk(256);
    const int MB = (Tt * Bb) / 128;     // 256 M-blocks

    // layer 0
    sgemm_bias<INN><<<dim3(Hh / 64, MB), blk>>>(x, W_ih0, b_ih, b_hh, bufA, Hh);
    rnn_scan<<<128, blk>>>(bufA, W_hh, h0, h_out);

    // layer 1
    sgemm_bias<Hh><<<dim3(Hh / 64, MB), blk>>>(bufA, W_ihr, b_ih + Hh, b_hh + Hh,
                                               bufB, Hh);
    rnn_scan<<<128, blk>>>(bufB, W_hh + Hh * Hh, h0 + Bb * Hh, h_out + Bb * Hh);

    // layer 2
    sgemm_bias<Hh><<<dim3(Hh / 64, MB), blk>>>(bufB, W_ihr + Hh * Hh,
                                               b_ih + 2 * Hh, b_hh + 2 * Hh,
                                               bufA, Hh);
    rnn_scan<<<128, blk>>>(bufA, W_hh + 2 * Hh * Hh, h0 + 2 * Bb * Hh,
                           h_out + 2 * Bb * Hh);

    // final linear: [32768,512] @ [128,512]^T + lin_b -> d_out
    sgemm_bias<Hh><<<dim3(OUTN / 64, MB), blk>>>(bufA, lin_W, lin_b, nullptr,
                                                 out, OUTN);
}